// round 16
// baseline (speedup 1.0000x reference)
#include <cuda_runtime.h>
#include <cuda_fp16.h>
#include <cstdint>

#define N_NODES 50000
#define N_EDGES 400000
#define F_IN    1024
#define F_HID   512
#define DEG_CAP 64

// ---------------- scratch (device globals; no runtime allocation) ----------
__device__ float g_dinv[N_NODES];
__device__ float g_H2  [N_NODES];                   // indexed by orig id
__device__ int   g_mask[N_NODES];
__device__ int   g_need[N_NODES];
__device__ int   g_ecnt[N_NODES];                   // in-degree counters
__device__ int   g_es  [(size_t)N_NODES * DEG_CAP]; // fixed-stride in-edge lists
__device__ int   g_rows [N_NODES];                  // compact -> orig (need set)
__device__ int   g_mrows[N_NODES];                  // masked node list
__device__ int   g_cnt;
__device__ int   g_mcnt;
// compacted fp16 split-A / single-B operands for the GEMM
__device__ __half g_XH[(size_t)N_NODES * F_IN];
__device__ __half g_XL[(size_t)N_NODES * F_IN];
__device__ __half g_WH[(size_t)F_HID * F_IN];       // W1^T [n][k]

// ---------------- fused init + convW ----------------------------------------
#define CONV_BLOCKS 512
#define INIT_BLOCKS ((N_NODES + 255) / 256)

__global__ __launch_bounds__(256) void k_init_convW(const float* __restrict__ x,
                                                    const float* __restrict__ W1,
                                                    float* __restrict__ out) {
    __shared__ float tile[32][33];
    if (blockIdx.x < CONV_BLOCKS) {
        int n0 = (blockIdx.x & 15) * 32, k0 = (blockIdx.x >> 4) * 32;
        int tx = threadIdx.x & 31, ty = threadIdx.x >> 5;   // 32 x 8
        #pragma unroll
        for (int j = 0; j < 32; j += 8)
            tile[ty + j][tx] = W1[(size_t)(k0 + ty + j) * F_HID + n0 + tx];
        __syncthreads();
        #pragma unroll
        for (int j = 0; j < 32; j += 8) {
            float v = tile[tx][ty + j];                     // W1[k0+tx][n0+ty+j]
            g_WH[(size_t)(n0 + ty + j) * F_IN + k0 + tx] = __float2half_rn(v);
        }
    } else {
        int i = (blockIdx.x - CONV_BLOCKS) * 256 + threadIdx.x;
        if (i < N_NODES) {
            int m = (__ldg(&x[(size_t)i * F_IN]) == 1.0f) ? 1 : 0;
            g_mask[i] = m;
            g_need[i] = m;
            g_ecnt[i] = 0;
            g_H2[i] = 0.0f;
            out[i] = 0.0f;
        }
        if (i == 0) { g_cnt = 0; g_mcnt = 0; }
    }
}

// single edge pass: degree counts, CSR fill, need marking (4 edges/thread)
__global__ __launch_bounds__(256) void k_graph(const int* __restrict__ ei) {
    int i = blockIdx.x * blockDim.x + threadIdx.x;     // quad index
    if (i * 4 >= N_EDGES) return;
    int4 s4 = *(const int4*)&ei[4 * i];
    int4 t4 = *(const int4*)&ei[N_EDGES + 4 * i];
    const int ss[4] = {s4.x, s4.y, s4.z, s4.w};
    const int tt[4] = {t4.x, t4.y, t4.z, t4.w};
    #pragma unroll
    for (int j = 0; j < 4; j++) {
        int s = ss[j], t = tt[j];
        if ((unsigned)t < N_NODES && (unsigned)s < N_NODES) {
            int slot = atomicAdd(&g_ecnt[t], 1);
            if (slot < DEG_CAP) g_es[(size_t)t * DEG_CAP + slot] = s;
            if (g_mask[t]) g_need[s] = 1;
        }
    }
}

// dinv; build compact lists with warp-aggregated atomics
__global__ void k_compact() {
    int i = blockIdx.x * blockDim.x + threadIdx.x;
    int lane = threadIdx.x & 31;
    bool valid = (i < N_NODES);
    bool need = false, mask = false;
    if (valid) {
        g_dinv[i] = rsqrtf((float)(g_ecnt[i] + 1));
        need = g_need[i] != 0;
        mask = g_mask[i] != 0;
    }
    unsigned mn = __ballot_sync(0xFFFFFFFFu, valid && need);
    if (mn) {
        int base = 0;
        if (lane == 0) base = atomicAdd(&g_cnt, __popc(mn));
        base = __shfl_sync(0xFFFFFFFFu, base, 0);
        if (valid && need)
            g_rows[base + __popc(mn & ((1u << lane) - 1))] = i;
    }
    unsigned mm = __ballot_sync(0xFFFFFFFFu, valid && mask);
    if (mm) {
        int base = 0;
        if (lane == 0) base = atomicAdd(&g_mcnt, __popc(mm));
        base = __shfl_sync(0xFFFFFFFFu, base, 0);
        if (valid && mask)
            g_mrows[base + __popc(mm & ((1u << lane) - 1))] = i;
    }
}

// ---------------- gather + fp16-split convert (8x batched for MLP) ----------
__global__ __launch_bounds__(256) void k_gather(const float* __restrict__ X) {
    int ch = threadIdx.x;                       // f4 chunk 0..255
    for (int pos = blockIdx.x; pos < g_cnt; pos += gridDim.x) {
        int row = g_rows[pos];
        float dt = g_dinv[row];
        float4 acc = *(const float4*)&X[(size_t)row * F_IN + 4 * ch];
        float c0 = dt * dt;
        acc.x *= c0; acc.y *= c0; acc.z *= c0; acc.w *= c0;
        const int* es = &g_es[(size_t)row * DEG_CAP];
        int ind = g_ecnt[row];
        if (ind > DEG_CAP) ind = DEG_CAP;
        int k = 0;
        for (; k + 8 <= ind; k += 8) {
            int4 i0 = *(const int4*)&es[k];
            int4 i1 = *(const int4*)&es[k + 4];
            const int sv[8] = {i0.x, i0.y, i0.z, i0.w, i1.x, i1.y, i1.z, i1.w};
            float4 v[8];
            #pragma unroll
            for (int j = 0; j < 8; j++)
                v[j] = *(const float4*)&X[(size_t)sv[j] * F_IN + 4 * ch];
            float cc[8];
            #pragma unroll
            for (int j = 0; j < 8; j++) cc[j] = g_dinv[sv[j]] * dt;
            #pragma unroll
            for (int j = 0; j < 8; j++) {
                acc.x += cc[j] * v[j].x; acc.y += cc[j] * v[j].y;
                acc.z += cc[j] * v[j].z; acc.w += cc[j] * v[j].w;
            }
        }
        for (; k + 4 <= ind; k += 4) {
            int4 i0 = *(const int4*)&es[k];
            const int sv[4] = {i0.x, i0.y, i0.z, i0.w};
            float4 v[4];
            #pragma unroll
            for (int j = 0; j < 4; j++)
                v[j] = *(const float4*)&X[(size_t)sv[j] * F_IN + 4 * ch];
            #pragma unroll
            for (int j = 0; j < 4; j++) {
                float c = g_dinv[sv[j]] * dt;
                acc.x += c * v[j].x; acc.y += c * v[j].y;
                acc.z += c * v[j].z; acc.w += c * v[j].w;
            }
        }
        for (; k < ind; k++) {
            int s = es[k];
            float c = g_dinv[s] * dt;
            float4 v = *(const float4*)&X[(size_t)s * F_IN + 4 * ch];
            acc.x += c * v.x; acc.y += c * v.y;
            acc.z += c * v.z; acc.w += c * v.w;
        }
        __half h0 = __float2half_rn(acc.x), h1 = __float2half_rn(acc.y);
        __half h2 = __float2half_rn(acc.z), h3 = __float2half_rn(acc.w);
        __half l0 = __float2half_rn(acc.x - __half2float(h0));
        __half l1 = __float2half_rn(acc.y - __half2float(h1));
        __half l2 = __float2half_rn(acc.z - __half2float(h2));
        __half l3 = __float2half_rn(acc.w - __half2float(h3));
        __half2* ph = (__half2*)&g_XH[(size_t)pos * F_IN + 4 * ch];
        __half2* pl = (__half2*)&g_XL[(size_t)pos * F_IN + 4 * ch];
        ph[0] = __halves2half2(h0, h1); ph[1] = __halves2half2(h2, h3);
        pl[0] = __halves2half2(l0, l1); pl[1] = __halves2half2(l2, l3);
    }
}

// ---------------- mma.sync GEMM helpers ------------------------------------
__device__ __forceinline__ uint32_t smem_u32(const void* p) {
    uint32_t a;
    asm("{ .reg .u64 t; cvta.to.shared.u64 t, %1; cvt.u32.u64 %0, t; }" : "=r"(a) : "l"(p));
    return a;
}
__device__ __forceinline__ uint32_t sw128(uint32_t o) { return o ^ ((o >> 3) & 0x70); }
__device__ __forceinline__ void cp16(uint32_t dst, const void* src, uint32_t sz) {
    asm volatile("cp.async.cg.shared.global [%0], [%1], 16, %2;"
                 :: "r"(dst), "l"(src), "r"(sz) : "memory");
}
__device__ __forceinline__ void cp_commit() {
    asm volatile("cp.async.commit_group;" ::: "memory");
}
__device__ __forceinline__ void ldm4(uint32_t* r, uint32_t a) {
    asm volatile("ldmatrix.sync.aligned.m8n8.x4.shared.b16 {%0,%1,%2,%3}, [%4];"
                 : "=r"(r[0]), "=r"(r[1]), "=r"(r[2]), "=r"(r[3]) : "r"(a));
}
__device__ __forceinline__ void mma16816(float* c, const uint32_t* a, uint32_t b0, uint32_t b1) {
    asm volatile(
        "mma.sync.aligned.m16n8k16.row.col.f32.f16.f16.f32 "
        "{%0,%1,%2,%3}, {%4,%5,%6,%7}, {%8,%9}, {%0,%1,%2,%3};"
        : "+f"(c[0]), "+f"(c[1]), "+f"(c[2]), "+f"(c[3])
        : "r"(a[0]), "r"(a[1]), "r"(a[2]), "r"(a[3]), "r"(b0), "r"(b1));
}

// ---------------- GEMM (128m x 256n tile, fp16 2-term) + fused GEMV epilogue
// stage: AH 16K | AL 16K | B 32K = 64KB, double buffered = 128KB
#define A_HI   0
#define A_LO   16384
#define B_HI   32768
#define STAGE_SZ 65536
#define SMEM_TOT (2 * STAGE_SZ)

__global__ __launch_bounds__(256, 1) void k_mmagemm(const float* __restrict__ b1,
                                                    const float* __restrict__ W2) {
    int cnt = g_cnt;
    int m0 = blockIdx.y * 128;
    if (m0 >= cnt) return;
    int n0 = blockIdx.x * 256;

    extern __shared__ __align__(1024) char smem[];
    uint32_t sb = smem_u32(smem);
    int tid = threadIdx.x, lane = tid & 31, wid = tid >> 5;
    int wm = wid & 3, wn = wid >> 2;            // warp tile 32x128

    float acc[2][16][4];
    #pragma unroll
    for (int mt = 0; mt < 2; mt++)
        #pragma unroll
        for (int nt = 0; nt < 16; nt++)
            #pragma unroll
            for (int i = 0; i < 4; i++) acc[mt][nt][i] = 0.0f;

    int rlA = (lane & 7) + ((lane & 8) ? 8 : 0);
    int chAsel = lane >> 4;
    int rlB = (lane & 7) + ((lane & 16) ? 8 : 0);
    int chBsel = (lane >> 3) & 1;

    auto load_stage = [&](int c, int s) {
        int k0 = c * 64;
        uint32_t base = sb + s * STAGE_SZ;
        #pragma unroll
        for (int j = 0; j < 4; j++) {          // A: 128 rows x 8 chunks (H+L)
            int v = tid + j * 256;
            int r = v >> 3, ch = v & 7;
            uint32_t sw = sw128((uint32_t)(r * 128 + ch * 16));
            int gm = m0 + r;
            uint32_t szA = (gm < cnt) ? 16u : 0u;
            size_t goffX = (size_t)gm * F_IN + k0 + ch * 8;
            cp16(base + A_HI + sw, &g_XH[goffX], szA);
            cp16(base + A_LO + sw, &g_XL[goffX], szA);
        }
        #pragma unroll
        for (int j = 0; j < 8; j++) {          // B: 256 rows x 8 chunks
            int v = tid + j * 256;
            int r = v >> 3, ch = v & 7;
            uint32_t sw = sw128((uint32_t)(r * 128 + ch * 16));
            size_t goffW = (size_t)(n0 + r) * F_IN + k0 + ch * 8;
            cp16(base + B_HI + sw, &g_WH[goffW], 16u);
        }
    };

    load_stage(0, 0);
    cp_commit();

    for (int c = 0; c < 16; ++c) {
        int s = c & 1;
        if (c < 15) { load_stage(c + 1, s ^ 1); cp_commit(); }
        if (c < 15) asm volatile("cp.async.wait_group 1;" ::: "memory");
        else        asm volatile("cp.async.wait_group 0;" ::: "memory");
        __syncthreads();

        uint32_t base = sb + s * STAGE_SZ;
        #pragma unroll
        for (int ks = 0; ks < 4; ++ks) {
            uint32_t aH[2][4], aL[2][4];
            #pragma unroll
            for (int mt = 0; mt < 2; mt++) {
                int rowA = wm * 32 + mt * 16 + rlA;
                int chA = ks * 2 + chAsel;
                uint32_t off = sw128((uint32_t)(rowA * 128 + chA * 16));
                ldm4(aH[mt], base + A_HI + off);
                ldm4(aL[mt], base + A_LO + off);
            }
            #pragma unroll
            for (int bt = 0; bt < 8; bt++) {
                uint32_t bH[4];
                int rowB = wn * 128 + bt * 16 + rlB;
                int chB = ks * 2 + chBsel;
                uint32_t off = sw128((uint32_t)(rowB * 128 + chB * 16));
                ldm4(bH, base + B_HI + off);
                #pragma unroll
                for (int h = 0; h < 2; h++) {
                    int nt = bt * 2 + h, i0 = h * 2;
                    #pragma unroll
                    for (int mt = 0; mt < 2; mt++) {
                        mma16816(acc[mt][nt], aH[mt], bH[i0], bH[i0 + 1]);
                        mma16816(acc[mt][nt], aL[mt], bH[i0], bH[i0 + 1]);
                    }
                }
            }
        }
        __syncthreads();
    }

    // fused epilogue: partial H2 = sum_cols relu(acc + b1) * W2, per row
    #pragma unroll
    for (int mt = 0; mt < 2; mt++) {
        int r_lo = m0 + wm * 32 + mt * 16 + lane / 4;
        float h_lo = 0.0f, h_hi = 0.0f;
        #pragma unroll
        for (int nt = 0; nt < 16; nt++) {
            int col = n0 + wn * 128 + nt * 8 + 2 * (lane % 4);
            float w0 = W2[col], w1 = W2[col + 1];
            float bb0 = b1[col], bb1 = b1[col + 1];
            h_lo += fmaxf(acc[mt][nt][0] + bb0, 0.0f) * w0
                  + fmaxf(acc[mt][nt][1] + bb1, 0.0f) * w1;
            h_hi += fmaxf(acc[mt][nt][2] + bb0, 0.0f) * w0
                  + fmaxf(acc[mt][nt][3] + bb1, 0.0f) * w1;
        }
        h_lo += __shfl_xor_sync(0xFFFFFFFFu, h_lo, 1);
        h_lo += __shfl_xor_sync(0xFFFFFFFFu, h_lo, 2);
        h_hi += __shfl_xor_sync(0xFFFFFFFFu, h_hi, 1);
        h_hi += __shfl_xor_sync(0xFFFFFFFFu, h_hi, 2);
        if ((lane & 3) == 0) {
            if (r_lo < cnt)     atomicAdd(&g_H2[g_rows[r_lo]], h_lo);
            if (r_lo + 8 < cnt) atomicAdd(&g_H2[g_rows[r_lo + 8]], h_hi);
        }
    }
}

// ---------------- output: masked-node CSR reduce ----------------------------
__global__ void k_out(const float* __restrict__ b2, float* __restrict__ out) {
    int gw = (blockIdx.x * blockDim.x + threadIdx.x) >> 5;
    int lane = threadIdx.x & 31;
    int nw = (gridDim.x * blockDim.x) >> 5;
    for (int p = gw; p < g_mcnt; p += nw) {
        int t = g_mrows[p];
        float dt = g_dinv[t];
        const int* es = &g_es[(size_t)t * DEG_CAP];
        int ind = g_ecnt[t];
        if (ind > DEG_CAP) ind = DEG_CAP;
        float sum = 0.0f;
        for (int k = lane; k < ind; k += 32) {
            int s = es[k];
            sum += g_dinv[s] * g_H2[s];
        }
        #pragma unroll
        for (int o = 16; o > 0; o >>= 1)
            sum += __shfl_xor_sync(0xFFFFFFFFu, sum, o);
        if (lane == 0)
            out[t] = b2[0] + dt * (sum + dt * g_H2[t]);
    }
}

// ---------------- launcher --------------------------------------------------
extern "C" void kernel_launch(void* const* d_in, const int* in_sizes, int n_in,
                              void* d_out, int out_size) {
    const float* x  = (const float*)d_in[0];
    const int*   ei = (const int*)d_in[1];
    const float* W1 = (const float*)d_in[2];
    const float* b1 = (const float*)d_in[3];
    const float* W2 = (const float*)d_in[4];
    const float* b2 = (const float*)d_in[5];
    float* out = (float*)d_out;

    cudaFuncSetAttribute(k_mmagemm, cudaFuncAttributeMaxDynamicSharedMemorySize, SMEM_TOT);

    k_init_convW<<<CONV_BLOCKS + INIT_BLOCKS, 256>>>(x, W1, out);
    k_graph  <<<(N_EDGES / 4 + 255) / 256, 256>>>(ei);
    k_compact<<<(N_NODES + 255) / 256, 256>>>();
    k_gather <<<8192, 256>>>(x);

    dim3 ggrid(F_HID / 256, (N_NODES + 127) / 128);
    k_mmagemm<<<ggrid, 256, SMEM_TOT>>>(b1, W2);

    k_out    <<<64, 256>>>(b2, out);
}

// round 17
// speedup vs baseline: 1.2162x; 1.2162x over previous
#include <cuda_runtime.h>
#include <cuda_fp16.h>
#include <cstdint>

#define N_NODES 50000
#define N_EDGES 400000
#define F_IN    1024
#define F_HID   512
#define DEG_CAP 64

// ---------------- scratch (device globals; no runtime allocation) ----------
__device__ float g_dinv[N_NODES];
__device__ float g_H2  [N_NODES];                   // indexed by orig id
__device__ int   g_mask[N_NODES];
__device__ int   g_need[N_NODES];
__device__ int   g_ecnt[N_NODES];                   // in-degree counters
__device__ int   g_es  [(size_t)N_NODES * DEG_CAP]; // fixed-stride in-edge lists
__device__ int   g_rows [N_NODES];                  // compact -> orig (need set)
__device__ int   g_mrows[N_NODES];                  // masked node list
__device__ int   g_cnt;
__device__ int   g_mcnt;
// compacted fp16 operands for the GEMM
__device__ __half g_XH[(size_t)N_NODES * F_IN];
__device__ __half g_WH[(size_t)F_HID * F_IN];       // W1^T [n][k]

// ---------------- fused init + convW ----------------------------------------
#define CONV_BLOCKS 512
#define INIT_BLOCKS ((N_NODES + 255) / 256)

__global__ __launch_bounds__(256) void k_init_convW(const float* __restrict__ x,
                                                    const float* __restrict__ W1,
                                                    float* __restrict__ out) {
    __shared__ float tile[32][33];
    if (blockIdx.x < CONV_BLOCKS) {
        int n0 = (blockIdx.x & 15) * 32, k0 = (blockIdx.x >> 4) * 32;
        int tx = threadIdx.x & 31, ty = threadIdx.x >> 5;   // 32 x 8
        #pragma unroll
        for (int j = 0; j < 32; j += 8)
            tile[ty + j][tx] = W1[(size_t)(k0 + ty + j) * F_HID + n0 + tx];
        __syncthreads();
        #pragma unroll
        for (int j = 0; j < 32; j += 8) {
            float v = tile[tx][ty + j];                     // W1[k0+tx][n0+ty+j]
            g_WH[(size_t)(n0 + ty + j) * F_IN + k0 + tx] = __float2half_rn(v);
        }
    } else {
        int i = (blockIdx.x - CONV_BLOCKS) * 256 + threadIdx.x;
        if (i < N_NODES) {
            int m = (__ldg(&x[(size_t)i * F_IN]) == 1.0f) ? 1 : 0;
            g_mask[i] = m;
            g_need[i] = m;
            g_ecnt[i] = 0;
            g_H2[i] = 0.0f;
            out[i] = 0.0f;
        }
        if (i == 0) { g_cnt = 0; g_mcnt = 0; }
    }
}

// single edge pass: degree counts, CSR fill, need marking (4 edges/thread)
__global__ __launch_bounds__(256) void k_graph(const int* __restrict__ ei) {
    int i = blockIdx.x * blockDim.x + threadIdx.x;     // quad index
    if (i * 4 >= N_EDGES) return;
    int4 s4 = *(const int4*)&ei[4 * i];
    int4 t4 = *(const int4*)&ei[N_EDGES + 4 * i];
    const int ss[4] = {s4.x, s4.y, s4.z, s4.w};
    const int tt[4] = {t4.x, t4.y, t4.z, t4.w};
    #pragma unroll
    for (int j = 0; j < 4; j++) {
        int s = ss[j], t = tt[j];
        if ((unsigned)t < N_NODES && (unsigned)s < N_NODES) {
            int slot = atomicAdd(&g_ecnt[t], 1);
            if (slot < DEG_CAP) g_es[(size_t)t * DEG_CAP + slot] = s;
            if (g_mask[t]) g_need[s] = 1;
        }
    }
}

// dinv; build compact lists with warp-aggregated atomics
__global__ void k_compact() {
    int i = blockIdx.x * blockDim.x + threadIdx.x;
    int lane = threadIdx.x & 31;
    bool valid = (i < N_NODES);
    bool need = false, mask = false;
    if (valid) {
        g_dinv[i] = rsqrtf((float)(g_ecnt[i] + 1));
        need = g_need[i] != 0;
        mask = g_mask[i] != 0;
    }
    unsigned mn = __ballot_sync(0xFFFFFFFFu, valid && need);
    if (mn) {
        int base = 0;
        if (lane == 0) base = atomicAdd(&g_cnt, __popc(mn));
        base = __shfl_sync(0xFFFFFFFFu, base, 0);
        if (valid && need)
            g_rows[base + __popc(mn & ((1u << lane) - 1))] = i;
    }
    unsigned mm = __ballot_sync(0xFFFFFFFFu, valid && mask);
    if (mm) {
        int base = 0;
        if (lane == 0) base = atomicAdd(&g_mcnt, __popc(mm));
        base = __shfl_sync(0xFFFFFFFFu, base, 0);
        if (valid && mask)
            g_mrows[base + __popc(mm & ((1u << lane) - 1))] = i;
    }
}

// ---------------- gather + fp16 convert (8x batched for MLP) ----------------
__global__ __launch_bounds__(256) void k_gather(const float* __restrict__ X) {
    int ch = threadIdx.x;                       // f4 chunk 0..255
    for (int pos = blockIdx.x; pos < g_cnt; pos += gridDim.x) {
        int row = g_rows[pos];
        float dt = g_dinv[row];
        float4 acc = *(const float4*)&X[(size_t)row * F_IN + 4 * ch];
        float c0 = dt * dt;
        acc.x *= c0; acc.y *= c0; acc.z *= c0; acc.w *= c0;
        const int* es = &g_es[(size_t)row * DEG_CAP];
        int ind = g_ecnt[row];
        if (ind > DEG_CAP) ind = DEG_CAP;
        int k = 0;
        for (; k + 8 <= ind; k += 8) {
            int4 i0 = *(const int4*)&es[k];
            int4 i1 = *(const int4*)&es[k + 4];
            const int sv[8] = {i0.x, i0.y, i0.z, i0.w, i1.x, i1.y, i1.z, i1.w};
            float4 v[8];
            #pragma unroll
            for (int j = 0; j < 8; j++)
                v[j] = *(const float4*)&X[(size_t)sv[j] * F_IN + 4 * ch];
            float cc[8];
            #pragma unroll
            for (int j = 0; j < 8; j++) cc[j] = g_dinv[sv[j]] * dt;
            #pragma unroll
            for (int j = 0; j < 8; j++) {
                acc.x += cc[j] * v[j].x; acc.y += cc[j] * v[j].y;
                acc.z += cc[j] * v[j].z; acc.w += cc[j] * v[j].w;
            }
        }
        for (; k + 4 <= ind; k += 4) {
            int4 i0 = *(const int4*)&es[k];
            const int sv[4] = {i0.x, i0.y, i0.z, i0.w};
            float4 v[4];
            #pragma unroll
            for (int j = 0; j < 4; j++)
                v[j] = *(const float4*)&X[(size_t)sv[j] * F_IN + 4 * ch];
            #pragma unroll
            for (int j = 0; j < 4; j++) {
                float c = g_dinv[sv[j]] * dt;
                acc.x += c * v[j].x; acc.y += c * v[j].y;
                acc.z += c * v[j].z; acc.w += c * v[j].w;
            }
        }
        for (; k < ind; k++) {
            int s = es[k];
            float c = g_dinv[s] * dt;
            float4 v = *(const float4*)&X[(size_t)s * F_IN + 4 * ch];
            acc.x += c * v.x; acc.y += c * v.y;
            acc.z += c * v.z; acc.w += c * v.w;
        }
        __half2* ph = (__half2*)&g_XH[(size_t)pos * F_IN + 4 * ch];
        ph[0] = __halves2half2(__float2half_rn(acc.x), __float2half_rn(acc.y));
        ph[1] = __halves2half2(__float2half_rn(acc.z), __float2half_rn(acc.w));
    }
}

// ---------------- mma.sync GEMM helpers ------------------------------------
__device__ __forceinline__ uint32_t smem_u32(const void* p) {
    uint32_t a;
    asm("{ .reg .u64 t; cvta.to.shared.u64 t, %1; cvt.u32.u64 %0, t; }" : "=r"(a) : "l"(p));
    return a;
}
__device__ __forceinline__ uint32_t sw128(uint32_t o) { return o ^ ((o >> 3) & 0x70); }
__device__ __forceinline__ void cp16(uint32_t dst, const void* src, uint32_t sz) {
    asm volatile("cp.async.cg.shared.global [%0], [%1], 16, %2;"
                 :: "r"(dst), "l"(src), "r"(sz) : "memory");
}
__device__ __forceinline__ void cp_commit() {
    asm volatile("cp.async.commit_group;" ::: "memory");
}
__device__ __forceinline__ void ldm4(uint32_t* r, uint32_t a) {
    asm volatile("ldmatrix.sync.aligned.m8n8.x4.shared.b16 {%0,%1,%2,%3}, [%4];"
                 : "=r"(r[0]), "=r"(r[1]), "=r"(r[2]), "=r"(r[3]) : "r"(a));
}
__device__ __forceinline__ void mma16816(float* c, const uint32_t* a, uint32_t b0, uint32_t b1) {
    asm volatile(
        "mma.sync.aligned.m16n8k16.row.col.f32.f16.f16.f32 "
        "{%0,%1,%2,%3}, {%4,%5,%6,%7}, {%8,%9}, {%0,%1,%2,%3};"
        : "+f"(c[0]), "+f"(c[1]), "+f"(c[2]), "+f"(c[3])
        : "r"(a[0]), "r"(a[1]), "r"(a[2]), "r"(a[3]), "r"(b0), "r"(b1));
}

// ---------------- GEMM (128m x 256n tile, pure fp16) + fused GEMV epilogue -
// stage: A 16K | B 32K = 48KB, double buffered = 96KB
#define A_HI   0
#define B_HI   16384
#define STAGE_SZ 49152
#define SMEM_TOT (2 * STAGE_SZ)

__global__ __launch_bounds__(256, 1) void k_mmagemm(const float* __restrict__ b1,
                                                    const float* __restrict__ W2) {
    int cnt = g_cnt;
    int m0 = blockIdx.y * 128;
    if (m0 >= cnt) return;
    int n0 = blockIdx.x * 256;

    extern __shared__ __align__(1024) char smem[];
    uint32_t sb = smem_u32(smem);
    int tid = threadIdx.x, lane = tid & 31, wid = tid >> 5;
    int wm = wid & 3, wn = wid >> 2;            // warp tile 32x128

    float acc[2][16][4];
    #pragma unroll
    for (int mt = 0; mt < 2; mt++)
        #pragma unroll
        for (int nt = 0; nt < 16; nt++)
            #pragma unroll
            for (int i = 0; i < 4; i++) acc[mt][nt][i] = 0.0f;

    int rlA = (lane & 7) + ((lane & 8) ? 8 : 0);
    int chAsel = lane >> 4;
    int rlB = (lane & 7) + ((lane & 16) ? 8 : 0);
    int chBsel = (lane >> 3) & 1;

    auto load_stage = [&](int c, int s) {
        int k0 = c * 64;
        uint32_t base = sb + s * STAGE_SZ;
        #pragma unroll
        for (int j = 0; j < 4; j++) {          // A: 128 rows x 8 chunks
            int v = tid + j * 256;
            int r = v >> 3, ch = v & 7;
            uint32_t sw = sw128((uint32_t)(r * 128 + ch * 16));
            int gm = m0 + r;
            uint32_t szA = (gm < cnt) ? 16u : 0u;
            size_t goffX = (size_t)gm * F_IN + k0 + ch * 8;
            cp16(base + A_HI + sw, &g_XH[goffX], szA);
        }
        #pragma unroll
        for (int j = 0; j < 8; j++) {          // B: 256 rows x 8 chunks
            int v = tid + j * 256;
            int r = v >> 3, ch = v & 7;
            uint32_t sw = sw128((uint32_t)(r * 128 + ch * 16));
            size_t goffW = (size_t)(n0 + r) * F_IN + k0 + ch * 8;
            cp16(base + B_HI + sw, &g_WH[goffW], 16u);
        }
    };

    load_stage(0, 0);
    cp_commit();

    for (int c = 0; c < 16; ++c) {
        int s = c & 1;
        if (c < 15) { load_stage(c + 1, s ^ 1); cp_commit(); }
        if (c < 15) asm volatile("cp.async.wait_group 1;" ::: "memory");
        else        asm volatile("cp.async.wait_group 0;" ::: "memory");
        __syncthreads();

        uint32_t base = sb + s * STAGE_SZ;
        #pragma unroll
        for (int ks = 0; ks < 4; ++ks) {
            uint32_t aH[2][4];
            #pragma unroll
            for (int mt = 0; mt < 2; mt++) {
                int rowA = wm * 32 + mt * 16 + rlA;
                int chA = ks * 2 + chAsel;
                uint32_t off = sw128((uint32_t)(rowA * 128 + chA * 16));
                ldm4(aH[mt], base + A_HI + off);
            }
            #pragma unroll
            for (int bt = 0; bt < 8; bt++) {
                uint32_t bH[4];
                int rowB = wn * 128 + bt * 16 + rlB;
                int chB = ks * 2 + chBsel;
                uint32_t off = sw128((uint32_t)(rowB * 128 + chB * 16));
                ldm4(bH, base + B_HI + off);
                #pragma unroll
                for (int h = 0; h < 2; h++) {
                    int nt = bt * 2 + h, i0 = h * 2;
                    #pragma unroll
                    for (int mt = 0; mt < 2; mt++)
                        mma16816(acc[mt][nt], aH[mt], bH[i0], bH[i0 + 1]);
                }
            }
        }
        __syncthreads();
    }

    // fused epilogue: partial H2 = sum_cols relu(acc + b1) * W2, per row
    #pragma unroll
    for (int mt = 0; mt < 2; mt++) {
        int r_lo = m0 + wm * 32 + mt * 16 + lane / 4;
        float h_lo = 0.0f, h_hi = 0.0f;
        #pragma unroll
        for (int nt = 0; nt < 16; nt++) {
            int col = n0 + wn * 128 + nt * 8 + 2 * (lane % 4);
            float w0 = W2[col], w1 = W2[col + 1];
            float bb0 = b1[col], bb1 = b1[col + 1];
            h_lo += fmaxf(acc[mt][nt][0] + bb0, 0.0f) * w0
                  + fmaxf(acc[mt][nt][1] + bb1, 0.0f) * w1;
            h_hi += fmaxf(acc[mt][nt][2] + bb0, 0.0f) * w0
                  + fmaxf(acc[mt][nt][3] + bb1, 0.0f) * w1;
        }
        h_lo += __shfl_xor_sync(0xFFFFFFFFu, h_lo, 1);
        h_lo += __shfl_xor_sync(0xFFFFFFFFu, h_lo, 2);
        h_hi += __shfl_xor_sync(0xFFFFFFFFu, h_hi, 1);
        h_hi += __shfl_xor_sync(0xFFFFFFFFu, h_hi, 2);
        if ((lane & 3) == 0) {
            if (r_lo < cnt)     atomicAdd(&g_H2[g_rows[r_lo]], h_lo);
            if (r_lo + 8 < cnt) atomicAdd(&g_H2[g_rows[r_lo + 8]], h_hi);
        }
    }
}

// ---------------- output: masked-node CSR reduce ----------------------------
__global__ void k_out(const float* __restrict__ b2, float* __restrict__ out) {
    int gw = (blockIdx.x * blockDim.x + threadIdx.x) >> 5;
    int lane = threadIdx.x & 31;
    int nw = (gridDim.x * blockDim.x) >> 5;
    for (int p = gw; p < g_mcnt; p += nw) {
        int t = g_mrows[p];
        float dt = g_dinv[t];
        const int* es = &g_es[(size_t)t * DEG_CAP];
        int ind = g_ecnt[t];
        if (ind > DEG_CAP) ind = DEG_CAP;
        float sum = 0.0f;
        for (int k = lane; k < ind; k += 32) {
            int s = es[k];
            sum += g_dinv[s] * g_H2[s];
        }
        #pragma unroll
        for (int o = 16; o > 0; o >>= 1)
            sum += __shfl_xor_sync(0xFFFFFFFFu, sum, o);
        if (lane == 0)
            out[t] = b2[0] + dt * (sum + dt * g_H2[t]);
    }
}

// ---------------- launcher --------------------------------------------------
extern "C" void kernel_launch(void* const* d_in, const int* in_sizes, int n_in,
                              void* d_out, int out_size) {
    const float* x  = (const float*)d_in[0];
    const int*   ei = (const int*)d_in[1];
    const float* W1 = (const float*)d_in[2];
    const float* b1 = (const float*)d_in[3];
    const float* W2 = (const float*)d_in[4];
    const float* b2 = (const float*)d_in[5];
    float* out = (float*)d_out;

    cudaFuncSetAttribute(k_mmagemm, cudaFuncAttributeMaxDynamicSharedMemorySize, SMEM_TOT);

    k_init_convW<<<CONV_BLOCKS + INIT_BLOCKS, 256>>>(x, W1, out);
    k_graph  <<<(N_EDGES / 4 + 255) / 256, 256>>>(ei);
    k_compact<<<(N_NODES + 255) / 256, 256>>>();
    k_gather <<<8192, 256>>>(x);

    dim3 ggrid(F_HID / 256, (N_NODES + 127) / 128);
    k_mmagemm<<<ggrid, 256, SMEM_TOT>>>(b1, W2);

    k_out    <<<64, 256>>>(b2, out);
}